// round 6
// baseline (speedup 1.0000x reference)
#include <cuda_runtime.h>
#include <mma.h>
#include <math.h>

using namespace nvcuda;

#define HDIM 256
#define MSGD 128
#define OBSD 64
#define ADIM 16
#define G3   768   // 3*HDIM
#define MAXN 20000

// ---------------- scratch (static device globals; no runtime allocation) ----
__device__ __align__(256) float g_x1 [MAXN * HDIM];
__device__ __align__(256) float g_x  [MAXN * HDIM];
__device__ __align__(256) float g_mx [MAXN * MSGD];
__device__ __align__(256) float g_c  [MAXN * MSGD];
__device__ __align__(256) float g_cnt[MAXN];
__device__ __align__(256) float g_gi [MAXN * G3];
__device__ __align__(256) float g_gh [MAXN * G3];

// ---------------- tf32 WMMA GEMM, double-buffered ----------------------------
// C[M x N] = act( A1@B1 (+ A2@B2) + bias ), A,B,C row-major.
// BM=128 BN=128 BK=16, 256 thr = 8 warps (4x2), warp tile 32x64 (2x4 wmma).
// tf32 rounding happens in the gmem->smem staging path; inner loop is pure mma.
#define LDA 20    // 16 + 4 pad
#define LDB 132   // 128 + 4 pad

template<bool HAS2, bool RELU>
__global__ void __launch_bounds__(256)
tgemm_kernel(const float* __restrict__ A1, int K1, const float* __restrict__ B1,
             const float* __restrict__ A2, int K2, const float* __restrict__ B2,
             const float* __restrict__ bias, float* __restrict__ C,
             int M, int N)
{
    constexpr int BM = 128, BN = 128, BK = 16;
    __shared__ float As[2][BM * LDA];
    __shared__ float Bs[2][BK * LDB];

    const int tid     = threadIdx.x;
    const int warpId  = tid >> 5;
    const int wy      = warpId & 3;        // 0..3 : m offset wy*32
    const int wx      = warpId >> 2;       // 0..1 : n offset wx*64
    const int rowBase = blockIdx.y * BM;
    const int colBase = blockIdx.x * BN;

    // ---- bias -> acc fragments (reuse Bs[0] as a 16 x BN bias tile) ----
    for (int i = tid; i < 16 * BN; i += 256) {
        int r = i >> 7, cc = i & 127;
        Bs[0][r * LDB + cc] = bias[colBase + cc];
    }
    __syncthreads();

    wmma::fragment<wmma::accumulator, 16, 16, 8, float> acc[2][4];
#pragma unroll
    for (int i = 0; i < 2; i++)
#pragma unroll
        for (int j = 0; j < 4; j++)
            wmma::load_matrix_sync(acc[i][j],
                &Bs[0][wx * 64 + j * 16], LDB, wmma::mem_row_major);
    __syncthreads();   // done reading bias tile before tile 0 overwrites it

    const int n1 = K1 / BK;
    const int nT = n1 + (HAS2 ? K2 / BK : 0);

    // per-thread staging indices
    const int ra  = (tid)          >> 2;          // A row for i=0 (0..63)
    const int ca  = (tid & 3)      << 2;          // A col 0/4/8/12
    const int rb  = (tid)          >> 5;          // B row for i=0 (0..7)
    const int cb  = (tid & 31)     << 2;          // B col 0..124

    float4 stgA[2], stgB[2];

    // ---- prologue: load + cvt + store tile 0 into buffer 0 ----
    {
        const float* A = A1; const float* B = B1; int K = K1; int k0 = 0;
        if (HAS2 && n1 == 0) { A = A2; B = B2; K = K2; }
#pragma unroll
        for (int i = 0; i < 2; i++) {
            int grow = rowBase + ra + i * 64;
            stgA[i] = (grow < M)
                ? *(const float4*)(A + (size_t)grow * K + k0 + ca)
                : make_float4(0.f, 0.f, 0.f, 0.f);
            stgB[i] = *(const float4*)(B + (size_t)(k0 + rb + i * 8) * N + colBase + cb);
        }
#pragma unroll
        for (int i = 0; i < 2; i++) {
            float* pa = &As[0][(ra + i * 64) * LDA + ca];
            pa[0] = wmma::__float_to_tf32(stgA[i].x);
            pa[1] = wmma::__float_to_tf32(stgA[i].y);
            pa[2] = wmma::__float_to_tf32(stgA[i].z);
            pa[3] = wmma::__float_to_tf32(stgA[i].w);
            float* pb = &Bs[0][(rb + i * 8) * LDB + cb];
            pb[0] = wmma::__float_to_tf32(stgB[i].x);
            pb[1] = wmma::__float_to_tf32(stgB[i].y);
            pb[2] = wmma::__float_to_tf32(stgB[i].z);
            pb[3] = wmma::__float_to_tf32(stgB[i].w);
        }
    }
    __syncthreads();

    int buf = 0;
    for (int t = 0; t < nT; t++) {
        // ---- issue gmem loads for tile t+1 (latency hidden behind mma) ----
        if (t + 1 < nT) {
            int tt = t + 1;
            const float* A; const float* B; int K; int k0;
            if (!HAS2 || tt < n1) { A = A1; B = B1; K = K1; k0 = tt * BK; }
            else                  { A = A2; B = B2; K = K2; k0 = (tt - n1) * BK; }
#pragma unroll
            for (int i = 0; i < 2; i++) {
                int grow = rowBase + ra + i * 64;
                stgA[i] = (grow < M)
                    ? *(const float4*)(A + (size_t)grow * K + k0 + ca)
                    : make_float4(0.f, 0.f, 0.f, 0.f);
                stgB[i] = *(const float4*)(B + (size_t)(k0 + rb + i * 8) * N + colBase + cb);
            }
        }

        // ---- mma over buffer buf (data already tf32-rounded) ----
#pragma unroll
        for (int kk = 0; kk < BK / 8; kk++) {
            wmma::fragment<wmma::matrix_a, 16, 16, 8,
                           wmma::precision::tf32, wmma::row_major> af[2];
            wmma::fragment<wmma::matrix_b, 16, 16, 8,
                           wmma::precision::tf32, wmma::row_major> bf[4];
#pragma unroll
            for (int i = 0; i < 2; i++)
                wmma::load_matrix_sync(af[i],
                    &As[buf][(wy * 32 + i * 16) * LDA + kk * 8], LDA);
#pragma unroll
            for (int j = 0; j < 4; j++)
                wmma::load_matrix_sync(bf[j],
                    &Bs[buf][(kk * 8) * LDB + wx * 64 + j * 16], LDB);
#pragma unroll
            for (int i = 0; i < 2; i++)
#pragma unroll
                for (int j = 0; j < 4; j++)
                    wmma::mma_sync(acc[i][j], af[i], bf[j], acc[i][j]);
        }

        // ---- cvt + store tile t+1 into the other buffer ----
        if (t + 1 < nT) {
            int nb = buf ^ 1;
#pragma unroll
            for (int i = 0; i < 2; i++) {
                float* pa = &As[nb][(ra + i * 64) * LDA + ca];
                pa[0] = wmma::__float_to_tf32(stgA[i].x);
                pa[1] = wmma::__float_to_tf32(stgA[i].y);
                pa[2] = wmma::__float_to_tf32(stgA[i].z);
                pa[3] = wmma::__float_to_tf32(stgA[i].w);
                float* pb = &Bs[nb][(rb + i * 8) * LDB + cb];
                pb[0] = wmma::__float_to_tf32(stgB[i].x);
                pb[1] = wmma::__float_to_tf32(stgB[i].y);
                pb[2] = wmma::__float_to_tf32(stgB[i].z);
                pb[3] = wmma::__float_to_tf32(stgB[i].w);
            }
        }
        __syncthreads();
        buf ^= 1;
    }

    // ---- epilogue: ReLU + store ----
#pragma unroll
    for (int i = 0; i < 2; i++) {
        int gm = rowBase + wy * 32 + i * 16;
        if (gm < M) {   // M % 16 == 0: fragment fully valid or fully out
#pragma unroll
            for (int j = 0; j < 4; j++) {
                if (RELU) {
#pragma unroll
                    for (int e = 0; e < acc[i][j].num_elements; e++)
                        acc[i][j].x[e] = fmaxf(acc[i][j].x[e], 0.f);
                }
                wmma::store_matrix_sync(
                    C + (size_t)gm * N + colBase + wx * 64 + j * 16,
                    acc[i][j], N, wmma::mem_row_major);
            }
        }
    }
}

// ---------------- edge scatter (vector red) ----------------------------------
__global__ void scatter_kernel(const float4* __restrict__ mx,
                               const int* __restrict__ src,
                               const int* __restrict__ dst,
                               float* __restrict__ sums,
                               float* __restrict__ cnt, int E)
{
    int w    = (blockIdx.x * blockDim.x + threadIdx.x) >> 5;
    int lane = threadIdx.x & 31;
    if (w >= E) return;
    int s = src[w];
    int d = dst[w];
    float4 v = mx[(size_t)s * 32 + lane];
    float* base = sums + (size_t)d * MSGD + lane * 4;
    asm volatile("red.global.add.v4.f32 [%0], {%1, %2, %3, %4};"
                 :: "l"(base), "f"(v.x), "f"(v.y), "f"(v.z), "f"(v.w)
                 : "memory");
    if (lane == 0) atomicAdd(cnt + d, 1.0f);
}

__global__ void div_kernel(float* __restrict__ c, const float* __restrict__ cnt, int Nn)
{
    int i = blockIdx.x * blockDim.x + threadIdx.x;
    if (i >= Nn * MSGD) return;
    float d = cnt[i >> 7];            // MSGD = 128
    c[i] = c[i] / fmaxf(d, 1.0f);
}

// ---------------- GRU gates --------------------------------------------------
__global__ void gates_kernel(const float* __restrict__ gi,
                             const float* __restrict__ gh,
                             const float* __restrict__ h,
                             float* __restrict__ hout, int M)
{
    int idx = blockIdx.x * blockDim.x + threadIdx.x;
    if (idx >= M * HDIM) return;
    int n = idx >> 8;                 // HDIM = 256
    int j = idx & 255;
    const float* gin = gi + (size_t)n * G3;
    const float* ghn = gh + (size_t)n * G3;
    float ir = gin[j], iz = gin[HDIM + j], in_ = gin[2 * HDIM + j];
    float hr = ghn[j], hz = ghn[HDIM + j], hn_ = ghn[2 * HDIM + j];
    float r  = 1.f / (1.f + expf(-(ir + hr)));
    float z  = 1.f / (1.f + expf(-(iz + hz)));
    float nn = tanhf(in_ + r * hn_);
    float hp = h[idx];
    hout[idx] = (1.f - z) * nn + z * hp;
}

// ---------------- q = h_new @ out_W + out_b (N=16, K=256) --------------------
__global__ void __launch_bounds__(256)
qout_kernel(const float* __restrict__ hn, const float* __restrict__ W,
            const float* __restrict__ b, float* __restrict__ q, int M)
{
    __shared__ float Ws[HDIM * ADIM];
    int tid = threadIdx.x;
    for (int i = tid; i < HDIM * ADIM; i += 256) Ws[i] = W[i];
    __syncthreads();

    int n = blockIdx.x * 256 + tid;
    if (n >= M) return;
    float acc[ADIM];
#pragma unroll
    for (int c = 0; c < ADIM; c++) acc[c] = b[c];
    const float* hr = hn + (size_t)n * HDIM;
    for (int k = 0; k < HDIM; k++) {
        float hv = hr[k];
#pragma unroll
        for (int c = 0; c < ADIM; c++) acc[c] = fmaf(hv, Ws[k * ADIM + c], acc[c]);
    }
    float* qr = q + (size_t)n * ADIM;
#pragma unroll
    for (int c = 0; c < ADIM; c++) qr[c] = acc[c];
}

// ---------------- launch ------------------------------------------------------
extern "C" void kernel_launch(void* const* d_in, const int* in_sizes, int n_in,
                              void* d_out, int out_size)
{
    const float* feat = (const float*)d_in[0];
    const float* h    = (const float*)d_in[1];
    const int*   src  = (const int*)d_in[2];
    const int*   dst  = (const int*)d_in[3];
    const float* eW0  = (const float*)d_in[4];
    const float* eb0  = (const float*)d_in[5];
    const float* eW1  = (const float*)d_in[6];
    const float* eb1  = (const float*)d_in[7];
    const float* mW   = (const float*)d_in[8];
    const float* mb   = (const float*)d_in[9];
    const float* Wih  = (const float*)d_in[10];
    const float* Whh  = (const float*)d_in[11];
    const float* bih  = (const float*)d_in[12];
    const float* bhh  = (const float*)d_in[13];
    const float* oW   = (const float*)d_in[14];
    const float* ob   = (const float*)d_in[15];

    const int Nn = in_sizes[1] / HDIM;   // 20000
    const int E  = in_sizes[2];          // 640000

    float *x1, *x, *mx, *c, *cnt, *gi, *gh;
    cudaGetSymbolAddress((void**)&x1,  g_x1);
    cudaGetSymbolAddress((void**)&x,   g_x);
    cudaGetSymbolAddress((void**)&mx,  g_mx);
    cudaGetSymbolAddress((void**)&c,   g_c);
    cudaGetSymbolAddress((void**)&cnt, g_cnt);
    cudaGetSymbolAddress((void**)&gi,  g_gi);
    cudaGetSymbolAddress((void**)&gh,  g_gh);

    float* out = (float*)d_out;
    float* q_out;
    float* h_out;
    if (out_size >= Nn * (ADIM + HDIM)) {        // (q, h_new) concatenated
        q_out = out;
        h_out = out + (size_t)Nn * ADIM;
    } else if (out_size == Nn * HDIM) {
        h_out = out;
        q_out = x1;
    } else {
        q_out = out;
        h_out = x1;
    }

    const int gy = (Nn + 127) / 128;
    dim3 blk(256);

    // x1 = relu(feat @ enc_W0 + enc_b0)     [N,64]@[64,256]
    tgemm_kernel<false, true><<<dim3(HDIM / 128, gy), blk>>>(
        feat, OBSD, eW0, nullptr, 0, nullptr, eb0, x1, Nn, HDIM);

    // x = relu(x1 @ enc_W1 + enc_b1)        [N,256]@[256,256]
    tgemm_kernel<false, true><<<dim3(HDIM / 128, gy), blk>>>(
        x1, HDIM, eW1, nullptr, 0, nullptr, eb1, x, Nn, HDIM);

    // mx = x @ Wx + h @ Wh + msg_b
    tgemm_kernel<true, false><<<dim3(MSGD / 128, gy), blk>>>(
        x, HDIM, mW, h, HDIM, mW + (size_t)HDIM * MSGD, mb, mx, Nn, MSGD);

    // segment mean over edges
    cudaMemsetAsync(c, 0, (size_t)Nn * MSGD * sizeof(float));
    cudaMemsetAsync(cnt, 0, (size_t)Nn * sizeof(float));
    scatter_kernel<<<(E * 32 + 255) / 256, 256>>>((const float4*)mx, src, dst, c, cnt, E);
    div_kernel<<<(Nn * MSGD + 255) / 256, 256>>>(c, cnt, Nn);

    // gi = [x | c] @ gru_Wih + bih          [N,384]@[384,768]
    tgemm_kernel<true, false><<<dim3(G3 / 128, gy), blk>>>(
        x, HDIM, Wih, c, MSGD, Wih + (size_t)HDIM * G3, bih, gi, Nn, G3);

    // gh = h @ gru_Whh + bhh                [N,256]@[256,768]
    tgemm_kernel<false, false><<<dim3(G3 / 128, gy), blk>>>(
        h, HDIM, Whh, nullptr, 0, nullptr, bhh, gh, Nn, G3);

    // GRU gates -> h_new
    gates_kernel<<<(Nn * HDIM + 255) / 256, 256>>>(gi, gh, h, h_out, Nn);

    // q = h_new @ out_W + out_b
    qout_kernel<<<(Nn + 255) / 256, 256>>>(h_out, oW, ob, q_out, Nn);
}

// round 7
// speedup vs baseline: 1.0546x; 1.0546x over previous
#include <cuda_runtime.h>
#include <mma.h>
#include <math.h>

using namespace nvcuda;

#define HDIM 256
#define MSGD 128
#define OBSD 64
#define ADIM 16
#define G3   768   // 3*HDIM
#define MAXN 20000

// ---------------- scratch (static device globals; no runtime allocation) ----
__device__ __align__(256) float g_x1 [MAXN * HDIM];
__device__ __align__(256) float g_x  [MAXN * HDIM];
__device__ __align__(256) float g_mx [MAXN * MSGD];
__device__ __align__(256) float g_c  [MAXN * MSGD];
__device__ __align__(256) float g_cnt[MAXN];
__device__ __align__(256) float g_gi [MAXN * G3];
__device__ __align__(256) float g_gh [MAXN * G3];

// ---------------- tf32 WMMA GEMM, double-buffered, occupancy-tuned ----------
// C[M x N] = act( A1@B1 (+ A2@B2) + bias ), A,B,C row-major.
// BM=128 BN=64 BK=16, 256 thr = 8 warps (4m x 2n), warp tile 32x32 (2x2 wmma).
// A staged k-major (transposed) -> col_major fragments, conflict-free loads.
// tf32 rounding in the staging path; inner loop is pure smem->frag->mma.
#define LDAT 132   // BM + 4
#define LDBT 68    // BN + 4

template<bool HAS2, bool RELU>
__global__ void __launch_bounds__(256)
tgemm_kernel(const float* __restrict__ A1, int K1, const float* __restrict__ B1,
             const float* __restrict__ A2, int K2, const float* __restrict__ B2,
             const float* __restrict__ bias, float* __restrict__ C,
             int M, int N)
{
    constexpr int BM = 128, BN = 64, BK = 16;
    __shared__ float As[2][BK * LDAT];   // [k][m] transposed
    __shared__ float Bs[2][BK * LDBT];   // [k][n]

    const int tid     = threadIdx.x;
    const int warpId  = tid >> 5;
    const int wy      = warpId & 3;        // m offset wy*32
    const int wx      = warpId >> 2;       // n offset wx*32
    const int rowBase = blockIdx.y * BM;
    const int colBase = blockIdx.x * BN;

    // ---- bias -> acc fragments (reuse Bs[0] as 16 x BN bias tile) ----
    for (int i = tid; i < 16 * BN; i += 256) {
        int r = i >> 6, cc = i & 63;
        Bs[0][r * LDBT + cc] = bias[colBase + cc];
    }
    __syncthreads();

    wmma::fragment<wmma::accumulator, 16, 16, 8, float> acc[2][2];
#pragma unroll
    for (int i = 0; i < 2; i++)
#pragma unroll
        for (int j = 0; j < 2; j++)
            wmma::load_matrix_sync(acc[i][j],
                &Bs[0][wx * 32 + j * 16], LDBT, wmma::mem_row_major);
    __syncthreads();   // finish reading bias before tile 0 overwrites it

    const int n1 = K1 / BK;
    const int nT = n1 + (HAS2 ? K2 / BK : 0);

    // staging indices: A tile 128x16 = 2 float4/thread, B tile 16x64 = 1
    const int ra = tid >> 2;            // 0..63  (rows ra, ra+64)
    const int ca = (tid & 3) << 2;      // k col 0/4/8/12
    const int rb = tid >> 4;            // 0..15
    const int cb = (tid & 15) << 2;     // 0..60

    float4 stgA[2], stgB;

    // ---- prologue: load + cvt + store tile 0 into buffer 0 ----
    {
        const float* A = A1; const float* B = B1; int K = K1;
        if (HAS2 && n1 == 0) { A = A2; B = B2; K = K2; }
#pragma unroll
        for (int i = 0; i < 2; i++) {
            int grow = rowBase + ra + i * 64;
            stgA[i] = (grow < M)
                ? *(const float4*)(A + (size_t)grow * K + ca)
                : make_float4(0.f, 0.f, 0.f, 0.f);
        }
        stgB = *(const float4*)(B + (size_t)rb * N + colBase + cb);
#pragma unroll
        for (int i = 0; i < 2; i++) {
            int m = ra + i * 64;
            As[0][(ca + 0) * LDAT + m] = wmma::__float_to_tf32(stgA[i].x);
            As[0][(ca + 1) * LDAT + m] = wmma::__float_to_tf32(stgA[i].y);
            As[0][(ca + 2) * LDAT + m] = wmma::__float_to_tf32(stgA[i].z);
            As[0][(ca + 3) * LDAT + m] = wmma::__float_to_tf32(stgA[i].w);
        }
        float* pb = &Bs[0][rb * LDBT + cb];
        pb[0] = wmma::__float_to_tf32(stgB.x);
        pb[1] = wmma::__float_to_tf32(stgB.y);
        pb[2] = wmma::__float_to_tf32(stgB.z);
        pb[3] = wmma::__float_to_tf32(stgB.w);
    }
    __syncthreads();

    int buf = 0;
    for (int t = 0; t < nT; t++) {
        // ---- issue gmem loads for tile t+1 ----
        if (t + 1 < nT) {
            int tt = t + 1;
            const float* A; const float* B; int K; int k0;
            if (!HAS2 || tt < n1) { A = A1; B = B1; K = K1; k0 = tt * BK; }
            else                  { A = A2; B = B2; K = K2; k0 = (tt - n1) * BK; }
#pragma unroll
            for (int i = 0; i < 2; i++) {
                int grow = rowBase + ra + i * 64;
                stgA[i] = (grow < M)
                    ? *(const float4*)(A + (size_t)grow * K + k0 + ca)
                    : make_float4(0.f, 0.f, 0.f, 0.f);
            }
            stgB = *(const float4*)(B + (size_t)(k0 + rb) * N + colBase + cb);
        }

        // ---- mma over buffer buf ----
#pragma unroll
        for (int kk = 0; kk < BK / 8; kk++) {
            wmma::fragment<wmma::matrix_a, 16, 16, 8,
                           wmma::precision::tf32, wmma::col_major> af[2];
            wmma::fragment<wmma::matrix_b, 16, 16, 8,
                           wmma::precision::tf32, wmma::row_major> bf[2];
#pragma unroll
            for (int i = 0; i < 2; i++)
                wmma::load_matrix_sync(af[i],
                    &As[buf][(kk * 8) * LDAT + wy * 32 + i * 16], LDAT);
#pragma unroll
            for (int j = 0; j < 2; j++)
                wmma::load_matrix_sync(bf[j],
                    &Bs[buf][(kk * 8) * LDBT + wx * 32 + j * 16], LDBT);
#pragma unroll
            for (int i = 0; i < 2; i++)
#pragma unroll
                for (int j = 0; j < 2; j++)
                    wmma::mma_sync(acc[i][j], af[i], bf[j], acc[i][j]);
        }

        // ---- cvt + store tile t+1 into the other buffer ----
        if (t + 1 < nT) {
            int nb = buf ^ 1;
#pragma unroll
            for (int i = 0; i < 2; i++) {
                int m = ra + i * 64;
                As[nb][(ca + 0) * LDAT + m] = wmma::__float_to_tf32(stgA[i].x);
                As[nb][(ca + 1) * LDAT + m] = wmma::__float_to_tf32(stgA[i].y);
                As[nb][(ca + 2) * LDAT + m] = wmma::__float_to_tf32(stgA[i].z);
                As[nb][(ca + 3) * LDAT + m] = wmma::__float_to_tf32(stgA[i].w);
            }
            float* pb = &Bs[nb][rb * LDBT + cb];
            pb[0] = wmma::__float_to_tf32(stgB.x);
            pb[1] = wmma::__float_to_tf32(stgB.y);
            pb[2] = wmma::__float_to_tf32(stgB.z);
            pb[3] = wmma::__float_to_tf32(stgB.w);
        }
        __syncthreads();
        buf ^= 1;
    }

    // ---- epilogue: ReLU + store ----
#pragma unroll
    for (int i = 0; i < 2; i++) {
        int gm = rowBase + wy * 32 + i * 16;
        if (gm < M) {   // M % 16 == 0: fragment fully valid or fully out
#pragma unroll
            for (int j = 0; j < 2; j++) {
                if (RELU) {
#pragma unroll
                    for (int e = 0; e < acc[i][j].num_elements; e++)
                        acc[i][j].x[e] = fmaxf(acc[i][j].x[e], 0.f);
                }
                wmma::store_matrix_sync(
                    C + (size_t)gm * N + colBase + wx * 32 + j * 16,
                    acc[i][j], N, wmma::mem_row_major);
            }
        }
    }
}

// ---------------- edge scatter (vector red) ----------------------------------
__global__ void scatter_kernel(const float4* __restrict__ mx,
                               const int* __restrict__ src,
                               const int* __restrict__ dst,
                               float* __restrict__ sums,
                               float* __restrict__ cnt, int E)
{
    int w    = (blockIdx.x * blockDim.x + threadIdx.x) >> 5;
    int lane = threadIdx.x & 31;
    if (w >= E) return;
    int s = src[w];
    int d = dst[w];
    float4 v = mx[(size_t)s * 32 + lane];
    float* base = sums + (size_t)d * MSGD + lane * 4;
    asm volatile("red.global.add.v4.f32 [%0], {%1, %2, %3, %4};"
                 :: "l"(base), "f"(v.x), "f"(v.y), "f"(v.z), "f"(v.w)
                 : "memory");
    if (lane == 0) atomicAdd(cnt + d, 1.0f);
}

__global__ void div_kernel(float* __restrict__ c, const float* __restrict__ cnt, int Nn)
{
    int i = blockIdx.x * blockDim.x + threadIdx.x;
    if (i >= Nn * MSGD) return;
    float d = cnt[i >> 7];            // MSGD = 128
    c[i] = c[i] / fmaxf(d, 1.0f);
}

// ---------------- GRU gates --------------------------------------------------
__global__ void gates_kernel(const float* __restrict__ gi,
                             const float* __restrict__ gh,
                             const float* __restrict__ h,
                             float* __restrict__ hout, int M)
{
    int idx = blockIdx.x * blockDim.x + threadIdx.x;
    if (idx >= M * HDIM) return;
    int n = idx >> 8;                 // HDIM = 256
    int j = idx & 255;
    const float* gin = gi + (size_t)n * G3;
    const float* ghn = gh + (size_t)n * G3;
    float ir = gin[j], iz = gin[HDIM + j], in_ = gin[2 * HDIM + j];
    float hr = ghn[j], hz = ghn[HDIM + j], hn_ = ghn[2 * HDIM + j];
    float r  = 1.f / (1.f + expf(-(ir + hr)));
    float z  = 1.f / (1.f + expf(-(iz + hz)));
    float nn = tanhf(in_ + r * hn_);
    float hp = h[idx];
    hout[idx] = (1.f - z) * nn + z * hp;
}

// ---------------- q = h_new @ out_W + out_b (N=16, K=256) --------------------
__global__ void __launch_bounds__(256)
qout_kernel(const float* __restrict__ hn, const float* __restrict__ W,
            const float* __restrict__ b, float* __restrict__ q, int M)
{
    __shared__ float Ws[HDIM * ADIM];
    int tid = threadIdx.x;
    for (int i = tid; i < HDIM * ADIM; i += 256) Ws[i] = W[i];
    __syncthreads();

    int n = blockIdx.x * 256 + tid;
    if (n >= M) return;
    float acc[ADIM];
#pragma unroll
    for (int c = 0; c < ADIM; c++) acc[c] = b[c];
    const float* hr = hn + (size_t)n * HDIM;
    for (int k = 0; k < HDIM; k++) {
        float hv = hr[k];
#pragma unroll
        for (int c = 0; c < ADIM; c++) acc[c] = fmaf(hv, Ws[k * ADIM + c], acc[c]);
    }
    float* qr = q + (size_t)n * ADIM;
#pragma unroll
    for (int c = 0; c < ADIM; c++) qr[c] = acc[c];
}

// ---------------- launch ------------------------------------------------------
extern "C" void kernel_launch(void* const* d_in, const int* in_sizes, int n_in,
                              void* d_out, int out_size)
{
    const float* feat = (const float*)d_in[0];
    const float* h    = (const float*)d_in[1];
    const int*   src  = (const int*)d_in[2];
    const int*   dst  = (const int*)d_in[3];
    const float* eW0  = (const float*)d_in[4];
    const float* eb0  = (const float*)d_in[5];
    const float* eW1  = (const float*)d_in[6];
    const float* eb1  = (const float*)d_in[7];
    const float* mW   = (const float*)d_in[8];
    const float* mb   = (const float*)d_in[9];
    const float* Wih  = (const float*)d_in[10];
    const float* Whh  = (const float*)d_in[11];
    const float* bih  = (const float*)d_in[12];
    const float* bhh  = (const float*)d_in[13];
    const float* oW   = (const float*)d_in[14];
    const float* ob   = (const float*)d_in[15];

    const int Nn = in_sizes[1] / HDIM;   // 20000
    const int E  = in_sizes[2];          // 640000

    float *x1, *x, *mx, *c, *cnt, *gi, *gh;
    cudaGetSymbolAddress((void**)&x1,  g_x1);
    cudaGetSymbolAddress((void**)&x,   g_x);
    cudaGetSymbolAddress((void**)&mx,  g_mx);
    cudaGetSymbolAddress((void**)&c,   g_c);
    cudaGetSymbolAddress((void**)&cnt, g_cnt);
    cudaGetSymbolAddress((void**)&gi,  g_gi);
    cudaGetSymbolAddress((void**)&gh,  g_gh);

    float* out = (float*)d_out;
    float* q_out;
    float* h_out;
    if (out_size >= Nn * (ADIM + HDIM)) {        // (q, h_new) concatenated
        q_out = out;
        h_out = out + (size_t)Nn * ADIM;
    } else if (out_size == Nn * HDIM) {
        h_out = out;
        q_out = x1;
    } else {
        q_out = out;
        h_out = x1;
    }

    const int gy = (Nn + 127) / 128;
    dim3 blk(256);

    // x1 = relu(feat @ enc_W0 + enc_b0)     [N,64]@[64,256]
    tgemm_kernel<false, true><<<dim3(HDIM / 64, gy), blk>>>(
        feat, OBSD, eW0, nullptr, 0, nullptr, eb0, x1, Nn, HDIM);

    // x = relu(x1 @ enc_W1 + enc_b1)        [N,256]@[256,256]
    tgemm_kernel<false, true><<<dim3(HDIM / 64, gy), blk>>>(
        x1, HDIM, eW1, nullptr, 0, nullptr, eb1, x, Nn, HDIM);

    // mx = x @ Wx + h @ Wh + msg_b
    tgemm_kernel<true, false><<<dim3(MSGD / 64, gy), blk>>>(
        x, HDIM, mW, h, HDIM, mW + (size_t)HDIM * MSGD, mb, mx, Nn, MSGD);

    // segment mean over edges
    cudaMemsetAsync(c, 0, (size_t)Nn * MSGD * sizeof(float));
    cudaMemsetAsync(cnt, 0, (size_t)Nn * sizeof(float));
    scatter_kernel<<<(E * 32 + 255) / 256, 256>>>((const float4*)mx, src, dst, c, cnt, E);
    div_kernel<<<(Nn * MSGD + 255) / 256, 256>>>(c, cnt, Nn);

    // gi = [x | c] @ gru_Wih + bih          [N,384]@[384,768]
    tgemm_kernel<true, false><<<dim3(G3 / 64, gy), blk>>>(
        x, HDIM, Wih, c, MSGD, Wih + (size_t)HDIM * G3, bih, gi, Nn, G3);

    // gh = h @ gru_Whh + bhh                [N,256]@[256,768]
    tgemm_kernel<false, false><<<dim3(G3 / 64, gy), blk>>>(
        h, HDIM, Whh, nullptr, 0, nullptr, bhh, gh, Nn, G3);

    // GRU gates -> h_new
    gates_kernel<<<(Nn * HDIM + 255) / 256, 256>>>(gi, gh, h, h_out, Nn);

    // q = h_new @ out_W + out_b
    qout_kernel<<<(Nn + 255) / 256, 256>>>(h_out, oW, ob, q_out, Nn);
}

// round 8
// speedup vs baseline: 1.2624x; 1.1971x over previous
#include <cuda_runtime.h>
#include <mma.h>
#include <math.h>

using namespace nvcuda;

#define HDIM 256
#define MSGD 128
#define OBSD 64
#define ADIM 16
#define G3   768   // 3*HDIM
#define MAXN 20000

// ---------------- scratch (static device globals; no runtime allocation) ----
__device__ __align__(256) float g_x1 [MAXN * HDIM];
__device__ __align__(256) float g_x  [MAXN * HDIM];
__device__ __align__(256) float g_mx [MAXN * MSGD];
__device__ __align__(256) float g_c  [MAXN * MSGD];
__device__ __align__(256) float g_cnt[MAXN];
__device__ __align__(256) float g_gi [MAXN * G3];
__device__ __align__(256) float g_gh [MAXN * G3];

// ---------------- cp.async helper --------------------------------------------
__device__ __forceinline__ void cp16(void* smem_dst, const void* gsrc, int src_bytes)
{
    unsigned d = (unsigned)__cvta_generic_to_shared(smem_dst);
    asm volatile("cp.async.cg.shared.global [%0], [%1], 16, %2;\n"
                 :: "r"(d), "l"(gsrc), "r"(src_bytes));
}
__device__ __forceinline__ void cp_commit()
{
    asm volatile("cp.async.commit_group;\n" ::: "memory");
}
__device__ __forceinline__ void cp_wait1()
{
    asm volatile("cp.async.wait_group 1;\n" ::: "memory");
}

// ---------------- tf32 WMMA GEMM, 3-stage cp.async pipeline ------------------
// C[M x N] = act( A1@B1 (+ A2@B2) + bias ), A,B,C row-major fp32.
// BM=128 BN=64 BK=16, 128 thr = 4 warps (2m x 2n), warp tile 64x32 (4x2 wmma).
// fp32 bits fed to tf32 HMMA directly (HW truncation); no cvt anywhere.
#define LDA 20   // 16 + 4 floats per A row (16B-aligned rows: 80B)
#define LDB 68   // 64 + 4 floats per B row (16B-aligned rows: 272B)

template<bool HAS2, bool RELU>
__global__ void __launch_bounds__(128)
tgemm_kernel(const float* __restrict__ A1, int K1, const float* __restrict__ B1,
             const float* __restrict__ A2, int K2, const float* __restrict__ B2,
             const float* __restrict__ bias, float* __restrict__ C,
             int M, int N)
{
    constexpr int BM = 128, BN = 64, BK = 16, STG = 3;
    __shared__ float As[STG][BM * LDA];   // row-major [m][k]
    __shared__ float Bs[STG][BK * LDB];   // row-major [k][n]
    __shared__ float BiasS[16 * LDB];

    const int tid     = threadIdx.x;
    const int warpId  = tid >> 5;
    const int wy      = warpId >> 1;       // 0..1 : m offset wy*64
    const int wx      = warpId & 1;        // 0..1 : n offset wx*32
    const int rowBase = blockIdx.y * BM;
    const int colBase = blockIdx.x * BN;

    // bias -> 16 replicated rows
    for (int i = tid; i < 16 * BN; i += 128) {
        int r = i >> 6, cc = i & 63;
        BiasS[r * LDB + cc] = bias[colBase + cc];
    }
    __syncthreads();

    wmma::fragment<wmma::accumulator, 16, 16, 8, float> acc[4][2];
#pragma unroll
    for (int i = 0; i < 4; i++)
#pragma unroll
        for (int j = 0; j < 2; j++)
            wmma::load_matrix_sync(acc[i][j],
                &BiasS[wx * 32 + j * 16], LDB, wmma::mem_row_major);

    const int n1 = K1 / BK;
    const int nT = n1 + (HAS2 ? K2 / BK : 0);

    // producer: A tile 128x16 = 512 float4 -> 4/thread; B 16x64 = 256 -> 2/thread
    auto issue = [&](int tt, int s) {
        const float* A; const float* B; int K; int k0;
        if (!HAS2 || tt < n1) { A = A1; B = B1; K = K1; k0 = tt * BK; }
        else                  { A = A2; B = B2; K = K2; k0 = (tt - n1) * BK; }
#pragma unroll
        for (int i2 = 0; i2 < 4; i2++) {
            int idx = tid + i2 * 128;
            int r   = idx >> 2;          // 0..127
            int c4  = (idx & 3) << 2;    // 0/4/8/12
            int grow = rowBase + r;
            cp16(&As[s][r * LDA + c4],
                 A + (size_t)grow * K + k0 + c4,
                 (grow < M) ? 16 : 0);
        }
#pragma unroll
        for (int i2 = 0; i2 < 2; i2++) {
            int idx = tid + i2 * 128;
            int r   = idx >> 4;          // 0..15
            int cc  = (idx & 15) << 2;   // 0..60
            cp16(&Bs[s][r * LDB + cc],
                 B + (size_t)(k0 + r) * N + colBase + cc, 16);
        }
    };

    // prologue: stages 0 and 1 (nT >= 4 always here)
    issue(0, 0); cp_commit();
    issue(1, 1); cp_commit();

    for (int t = 0; t < nT; t++) {
        cp_wait1();            // stage t complete (<=1 newer group pending)
        __syncthreads();       // all threads' stage-t data visible; prev consume done
        const int buf = t % STG;

#pragma unroll
        for (int kk = 0; kk < BK / 8; kk++) {
            wmma::fragment<wmma::matrix_a, 16, 16, 8,
                           wmma::precision::tf32, wmma::row_major> af[4];
            wmma::fragment<wmma::matrix_b, 16, 16, 8,
                           wmma::precision::tf32, wmma::row_major> bf[2];
#pragma unroll
            for (int i = 0; i < 4; i++)
                wmma::load_matrix_sync(af[i],
                    &As[buf][(wy * 64 + i * 16) * LDA + kk * 8], LDA);
#pragma unroll
            for (int j = 0; j < 2; j++)
                wmma::load_matrix_sync(bf[j],
                    &Bs[buf][(kk * 8) * LDB + wx * 32 + j * 16], LDB);
#pragma unroll
            for (int i = 0; i < 4; i++)
#pragma unroll
                for (int j = 0; j < 2; j++)
                    wmma::mma_sync(acc[i][j], af[i], bf[j], acc[i][j]);
        }

        if (t + 2 < nT) issue(t + 2, (t + 2) % STG);
        cp_commit();           // commit every iter (possibly empty) -> uniform counts
    }

    // epilogue: ReLU + store
#pragma unroll
    for (int i = 0; i < 4; i++) {
        int gm = rowBase + wy * 64 + i * 16;
        if (gm < M) {   // M % 16 == 0: fragment fully valid or fully out
#pragma unroll
            for (int j = 0; j < 2; j++) {
                if (RELU) {
#pragma unroll
                    for (int e = 0; e < acc[i][j].num_elements; e++)
                        acc[i][j].x[e] = fmaxf(acc[i][j].x[e], 0.f);
                }
                wmma::store_matrix_sync(
                    C + (size_t)gm * N + colBase + wx * 32 + j * 16,
                    acc[i][j], N, wmma::mem_row_major);
            }
        }
    }
}

// ---------------- edge scatter (vector red) ----------------------------------
__global__ void scatter_kernel(const float4* __restrict__ mx,
                               const int* __restrict__ src,
                               const int* __restrict__ dst,
                               float* __restrict__ sums,
                               float* __restrict__ cnt, int E)
{
    int w    = (blockIdx.x * blockDim.x + threadIdx.x) >> 5;
    int lane = threadIdx.x & 31;
    if (w >= E) return;
    int s = src[w];
    int d = dst[w];
    float4 v = mx[(size_t)s * 32 + lane];
    float* base = sums + (size_t)d * MSGD + lane * 4;
    asm volatile("red.global.add.v4.f32 [%0], {%1, %2, %3, %4};"
                 :: "l"(base), "f"(v.x), "f"(v.y), "f"(v.z), "f"(v.w)
                 : "memory");
    if (lane == 0) atomicAdd(cnt + d, 1.0f);
}

__global__ void div_kernel(float* __restrict__ c, const float* __restrict__ cnt, int Nn)
{
    int i = blockIdx.x * blockDim.x + threadIdx.x;
    if (i >= Nn * MSGD) return;
    float d = cnt[i >> 7];            // MSGD = 128
    c[i] = c[i] / fmaxf(d, 1.0f);
}

// ---------------- GRU gates --------------------------------------------------
__global__ void gates_kernel(const float* __restrict__ gi,
                             const float* __restrict__ gh,
                             const float* __restrict__ h,
                             float* __restrict__ hout, int M)
{
    int idx = blockIdx.x * blockDim.x + threadIdx.x;
    if (idx >= M * HDIM) return;
    int n = idx >> 8;                 // HDIM = 256
    int j = idx & 255;
    const float* gin = gi + (size_t)n * G3;
    const float* ghn = gh + (size_t)n * G3;
    float ir = gin[j], iz = gin[HDIM + j], in_ = gin[2 * HDIM + j];
    float hr = ghn[j], hz = ghn[HDIM + j], hn_ = ghn[2 * HDIM + j];
    float r  = 1.f / (1.f + expf(-(ir + hr)));
    float z  = 1.f / (1.f + expf(-(iz + hz)));
    float nn = tanhf(in_ + r * hn_);
    float hp = h[idx];
    hout[idx] = (1.f - z) * nn + z * hp;
}

// ---------------- q = h_new @ out_W + out_b (N=16, K=256) --------------------
__global__ void __launch_bounds__(256)
qout_kernel(const float* __restrict__ hn, const float* __restrict__ W,
            const float* __restrict__ b, float* __restrict__ q, int M)
{
    __shared__ float Ws[HDIM * ADIM];
    int tid = threadIdx.x;
    for (int i = tid; i < HDIM * ADIM; i += 256) Ws[i] = W[i];
    __syncthreads();

    int n = blockIdx.x * 256 + tid;
    if (n >= M) return;
    float acc[ADIM];
#pragma unroll
    for (int c = 0; c < ADIM; c++) acc[c] = b[c];
    const float* hr = hn + (size_t)n * HDIM;
    for (int k = 0; k < HDIM; k++) {
        float hv = hr[k];
#pragma unroll
        for (int c = 0; c < ADIM; c++) acc[c] = fmaf(hv, Ws[k * ADIM + c], acc[c]);
    }
    float* qr = q + (size_t)n * ADIM;
#pragma unroll
    for (int c = 0; c < ADIM; c++) qr[c] = acc[c];
}

// ---------------- launch ------------------------------------------------------
extern "C" void kernel_launch(void* const* d_in, const int* in_sizes, int n_in,
                              void* d_out, int out_size)
{
    const float* feat = (const float*)d_in[0];
    const float* h    = (const float*)d_in[1];
    const int*   src  = (const int*)d_in[2];
    const int*   dst  = (const int*)d_in[3];
    const float* eW0  = (const float*)d_in[4];
    const float* eb0  = (const float*)d_in[5];
    const float* eW1  = (const float*)d_in[6];
    const float* eb1  = (const float*)d_in[7];
    const float* mW   = (const float*)d_in[8];
    const float* mb   = (const float*)d_in[9];
    const float* Wih  = (const float*)d_in[10];
    const float* Whh  = (const float*)d_in[11];
    const float* bih  = (const float*)d_in[12];
    const float* bhh  = (const float*)d_in[13];
    const float* oW   = (const float*)d_in[14];
    const float* ob   = (const float*)d_in[15];

    const int Nn = in_sizes[1] / HDIM;   // 20000
    const int E  = in_sizes[2];          // 640000

    float *x1, *x, *mx, *c, *cnt, *gi, *gh;
    cudaGetSymbolAddress((void**)&x1,  g_x1);
    cudaGetSymbolAddress((void**)&x,   g_x);
    cudaGetSymbolAddress((void**)&mx,  g_mx);
    cudaGetSymbolAddress((void**)&c,   g_c);
    cudaGetSymbolAddress((void**)&cnt, g_cnt);
    cudaGetSymbolAddress((void**)&gi,  g_gi);
    cudaGetSymbolAddress((void**)&gh,  g_gh);

    float* out = (float*)d_out;
    float* q_out;
    float* h_out;
    if (out_size >= Nn * (ADIM + HDIM)) {        // (q, h_new) concatenated
        q_out = out;
        h_out = out + (size_t)Nn * ADIM;
    } else if (out_size == Nn * HDIM) {
        h_out = out;
        q_out = x1;
    } else {
        q_out = out;
        h_out = x1;
    }

    const int gy = (Nn + 127) / 128;
    dim3 blk(128);

    // x1 = relu(feat @ enc_W0 + enc_b0)     [N,64]@[64,256]
    tgemm_kernel<false, true><<<dim3(HDIM / 64, gy), blk>>>(
        feat, OBSD, eW0, nullptr, 0, nullptr, eb0, x1, Nn, HDIM);

    // x = relu(x1 @ enc_W1 + enc_b1)        [N,256]@[256,256]
    tgemm_kernel<false, true><<<dim3(HDIM / 64, gy), blk>>>(
        x1, HDIM, eW1, nullptr, 0, nullptr, eb1, x, Nn, HDIM);

    // mx = x @ Wx + h @ Wh + msg_b
    tgemm_kernel<true, false><<<dim3(MSGD / 64, gy), blk>>>(
        x, HDIM, mW, h, HDIM, mW + (size_t)HDIM * MSGD, mb, mx, Nn, MSGD);

    // segment mean over edges
    cudaMemsetAsync(c, 0, (size_t)Nn * MSGD * sizeof(float));
    cudaMemsetAsync(cnt, 0, (size_t)Nn * sizeof(float));
    scatter_kernel<<<(E * 32 + 255) / 256, 256>>>((const float4*)mx, src, dst, c, cnt, E);
    div_kernel<<<(Nn * MSGD + 255) / 256, 256>>>(c, cnt, Nn);

    // gi = [x | c] @ gru_Wih + bih          [N,384]@[384,768]
    tgemm_kernel<true, false><<<dim3(G3 / 64, gy), blk>>>(
        x, HDIM, Wih, c, MSGD, Wih + (size_t)HDIM * G3, bih, gi, Nn, G3);

    // gh = h @ gru_Whh + bhh                [N,256]@[256,768]
    tgemm_kernel<false, false><<<dim3(G3 / 64, gy), blk>>>(
        h, HDIM, Whh, nullptr, 0, nullptr, bhh, gh, Nn, G3);

    // GRU gates -> h_new
    gates_kernel<<<(Nn * HDIM + 255) / 256, 256>>>(gi, gh, h, h_out, Nn);

    // q = h_new @ out_W + out_b
    qout_kernel<<<(Nn + 255) / 256, 256>>>(h_out, oW, ob, q_out, Nn);
}